// round 4
// baseline (speedup 1.0000x reference)
#include <cuda_runtime.h>
#include <cuda_bf16.h>

// NeRF render + accumulate, replicating XLA:CPU's cumsum rounding.
//
// Hypothesis: reference jnp.cumsum runs on CPU -> reduce_window lowering ->
// XLA ReduceWindowRewriter (base_length=16) radix-16 tree:
//   inner[r,j] = foldleft(x[16r .. 16r+j])        (init 0, ascending)
//   tot[r]     = inner[r,15]
//   outer      = cum(tot)  (recursive; n<=16 -> direct foldleft scan)
//   c[16r+j]   = (r==0) ? inner[r,j] : inner[r,j] + outer[r-1]
// All critical-path FP ops via __fmul_rn/__fadd_rn/__fsub_rn so nvcc cannot
// contract them into FMAs (the reference rounds the mul separately).
//
// Then: excl_i = c_i - sdt_i ; d = excl_i - excl_lead ; w = exp(-d)*(1-exp(-sdt)),
// segment-reduced per ray (warp per ray, sorted indices, binary-searched bounds).

#define MAX_S   (1 << 22)
#define ARENA_F 300000          // sum of level sizes for S=2^22 is 279,620
#define WARPS_PER_BLOCK 8
#define K4_THREADS (WARPS_PER_BLOCK * 32)

__device__ float g_sdt[MAX_S];
__device__ float g_c[MAX_S];
__device__ float g_lvl[ARENA_F];

// ---------------------------------------------------------------------------
// up0: sdt = fmul(sigma, fsub(t_end, t_start)); per-16 row totals (foldleft)
// ---------------------------------------------------------------------------
__global__ void k_up0(const float* __restrict__ ts,
                      const float* __restrict__ te,
                      const float* __restrict__ sg,
                      float* __restrict__ out_tot, int S)
{
    const int r = blockIdx.x * blockDim.x + threadIdx.x;
    const int R = (S + 15) >> 4;
    if (r >= R) return;
    const int base = r << 4;
    const int lim  = min(16, S - base);
    float acc = 0.0f;
    #pragma unroll
    for (int k = 0; k < 16; k++) {
        if (k < lim) {
            const int i = base + k;
            const float v = __fmul_rn(sg[i], __fsub_rn(te[i], ts[i]));
            g_sdt[i] = v;
            acc = __fadd_rn(acc, v);
        }
    }
    out_tot[r] = acc;
}

// up (generic level): row totals of 16-element rows
__global__ void k_up(const float* __restrict__ in, int n, float* __restrict__ out)
{
    const int r = blockIdx.x * blockDim.x + threadIdx.x;
    const int R = (n + 15) >> 4;
    if (r >= R) return;
    const int base = r << 4;
    const int lim  = min(16, n - base);
    float acc = 0.0f;
    #pragma unroll
    for (int k = 0; k < 16; k++)
        if (k < lim) acc = __fadd_rn(acc, in[base + k]);
    out[r] = acc;
}

// base case: n <= 16, sequential inclusive foldleft scan in place
__global__ void k_base(float* __restrict__ a, int n)
{
    if (blockIdx.x == 0 && threadIdx.x == 0) {
        float acc = 0.0f;
        for (int i = 0; i < n; i++) {
            acc = __fadd_rn(acc, a[i]);
            a[i] = acc;
        }
    }
}

// down (generic level l>=1): in-place scan of a using scanned next level
__global__ void k_down(float* __restrict__ a, int n, const float* __restrict__ snext)
{
    const int r = blockIdx.x * blockDim.x + threadIdx.x;
    const int R = (n + 15) >> 4;
    if (r >= R) return;
    const int base = r << 4;
    const int lim  = min(16, n - base);
    float acc = 0.0f;
    if (r == 0) {
        #pragma unroll
        for (int k = 0; k < 16; k++)
            if (k < lim) { acc = __fadd_rn(acc, a[base + k]); a[base + k] = acc; }
    } else {
        const float p = snext[r - 1];
        #pragma unroll
        for (int k = 0; k < 16; k++)
            if (k < lim) { acc = __fadd_rn(acc, a[base + k]); a[base + k] = __fadd_rn(acc, p); }
    }
}

// down0: final cumsum c from g_sdt + level-1 scan
__global__ void k_down0(int S, const float* __restrict__ s1)
{
    const int r = blockIdx.x * blockDim.x + threadIdx.x;
    const int R = (S + 15) >> 4;
    if (r >= R) return;
    const int base = r << 4;
    const int lim  = min(16, S - base);
    float acc = 0.0f;
    if (r == 0) {
        #pragma unroll
        for (int k = 0; k < 16; k++)
            if (k < lim) { acc = __fadd_rn(acc, g_sdt[base + k]); g_c[base + k] = acc; }
    } else {
        const float p = s1[r - 1];
        #pragma unroll
        for (int k = 0; k < 16; k++)
            if (k < lim) { acc = __fadd_rn(acc, g_sdt[base + k]); g_c[base + k] = __fadd_rn(acc, p); }
    }
}

// ---------------------------------------------------------------------------
// render: warp per ray
// ---------------------------------------------------------------------------
__device__ __forceinline__ int lower_bound_i32(const int* __restrict__ a, int n, int key) {
    int lo = 0, hi = n;
    while (lo < hi) {
        const int mid = (lo + hi) >> 1;
        if (__ldg(a + mid) < key) lo = mid + 1;
        else                      hi = mid;
    }
    return lo;
}

__global__ __launch_bounds__(K4_THREADS)
void k4_render(const float* __restrict__ hdr,
               const int*   __restrict__ ray_indices,
               float*       __restrict__ out,
               int S, int n_rays)
{
    const int r    = blockIdx.x * WARPS_PER_BLOCK + (threadIdx.x >> 5);
    const int lane = threadIdx.x & 31;
    if (r >= n_rays) return;

    int b = 0;
    if (lane < 2) b = lower_bound_i32(ray_indices, S, r + lane);
    const int start = __shfl_sync(0xffffffffu, b, 0);
    const int end   = __shfl_sync(0xffffffffu, b, 1);

    float e_lead = 0.0f;
    if (lane == 0 && start < end)
        e_lead = __fsub_rn(g_c[start], g_sdt[start]);   // excl[lead]
    e_lead = __shfl_sync(0xffffffffu, e_lead, 0);

    float opac = 0.0f, cr = 0.0f, cg = 0.0f, cb = 0.0f;

    for (int base = start; base < end; base += 32) {
        const int i = base + lane;
        if (i < end) {
            const float s  = g_sdt[i];
            const float ci = g_c[i];
            const float d  = __fsub_rn(__fsub_rn(ci, s), e_lead); // excl_i - excl_lead
            const float trans = expf(-d);
            const float alpha = 1.0f - expf(-s);
            const float w = __fmul_rn(trans, alpha);
            const long hoff = 3l * i;
            opac += w;
            cr += w * __ldg(hdr + hoff + 0);
            cg += w * __ldg(hdr + hoff + 1);
            cb += w * __ldg(hdr + hoff + 2);
        }
    }

    #pragma unroll
    for (int o = 16; o > 0; o >>= 1) {
        opac += __shfl_xor_sync(0xffffffffu, opac, o);
        cr   += __shfl_xor_sync(0xffffffffu, cr,   o);
        cg   += __shfl_xor_sync(0xffffffffu, cg,   o);
        cb   += __shfl_xor_sync(0xffffffffu, cb,   o);
    }

    if (lane == 0)
        reinterpret_cast<float4*>(out)[r] = make_float4(opac, cr, cg, cb);
}

// ---------------------------------------------------------------------------
extern "C" void kernel_launch(void* const* d_in, const int* in_sizes, int n_in,
                              void* d_out, int out_size)
{
    const float* t_starts    = (const float*)d_in[0];
    const float* t_ends      = (const float*)d_in[1];
    const float* sigmas      = (const float*)d_in[2];
    const float* hdr         = (const float*)d_in[3];
    const int*   ray_indices = (const int*)  d_in[4];
    float*       out         = (float*)d_out;

    const int S      = in_sizes[0];
    const int n_rays = out_size / 4;

    // Level sizes: n[0]=S; n[l+1]=ceil(n[l]/16) while n[l] > 16.
    int n[10]; int L = 0;
    n[0] = S;
    while (n[L] > 16 && L < 8) { n[L + 1] = (n[L] + 15) >> 4; L++; }
    // Arena offsets for levels 1..L
    int off[10]; off[1] = 0;
    for (int l = 2; l <= L; l++) off[l] = off[l - 1] + n[l - 1];

    float* lvl_base = nullptr;
    cudaGetSymbolAddress((void**)&lvl_base, g_lvl);

    const int T = 256;
    // upsweep
    {
        const int R = (S + 15) >> 4;
        k_up0<<<(R + T - 1) / T, T>>>(t_starts, t_ends, sigmas, lvl_base + off[1], S);
    }
    for (int l = 1; l < L; l++) {
        const int R = (n[l] + 15) >> 4;
        k_up<<<(R + T - 1) / T, T>>>(lvl_base + off[l], n[l], lvl_base + off[l + 1]);
    }
    // base scan
    k_base<<<1, 32>>>(lvl_base + off[L], n[L]);
    // downsweep
    for (int l = L - 1; l >= 1; l--) {
        const int R = (n[l] + 15) >> 4;
        k_down<<<(R + T - 1) / T, T>>>(lvl_base + off[l], n[l], lvl_base + off[l + 1]);
    }
    {
        const int R = (S + 15) >> 4;
        k_down0<<<(R + T - 1) / T, T>>>(S, lvl_base + off[1]);
    }
    // render
    const int blocks = (n_rays + WARPS_PER_BLOCK - 1) / WARPS_PER_BLOCK;
    k4_render<<<blocks, K4_THREADS>>>(hdr, ray_indices, out, S, n_rays);
}

// round 5
// speedup vs baseline: 1.8344x; 1.8344x over previous
#include <cuda_runtime.h>
#include <cuda_bf16.h>

// NeRF render + accumulate, bit-matching XLA:CPU's ReduceWindowRewriter
// (base_length=16) radix-16 cumsum tree. PASSED R4 @ rel_err 1.5e-7.
// This round: launch fusion + float4 vectorization + precomputed segment
// bounds. All rounding-critical op sequences are IDENTICAL to R4:
//   sdt_i = fmul(sigma_i, fsub(te_i, ts_i))
//   row fold-left with fadd, radix-16 up/down tree, c = fadd(acc, prefix)
//   excl = fsub(c, sdt); d = fsub(excl_i, excl_lead); w = fmul(exp(-d), 1-exp(-sdt))

#define MAX_S    (1 << 22)
#define N1_MAX   (MAX_S / 16)      // 262144
#define N2_MAX   (N1_MAX / 16)     // 16384
#define MAX_RAYS (1 << 18)
#define WARPS_PER_BLOCK 8
#define K6_THREADS (WARPS_PER_BLOCK * 32)

__device__ __align__(16) float g_sdt[MAX_S];
__device__ __align__(16) float g_c[MAX_S];
__device__ __align__(16) float g_l1[N1_MAX];
__device__ __align__(16) float g_l2[N2_MAX];
__device__ int g_rs[MAX_RAYS];
__device__ int g_re[MAX_RAYS];

// ---------------------------------------------------------------------------
// K1: sdt = fmul(sg, fsub(te, ts)); fold-left per 16-row -> g_l1.
// Vectorized float4 path for full rows; scalar tail. Also zero-inits bounds.
// ---------------------------------------------------------------------------
__global__ __launch_bounds__(256)
void k1_sdt_fold(const float* __restrict__ ts,
                 const float* __restrict__ te,
                 const float* __restrict__ sg,
                 int S, int n_rays)
{
    const int r = blockIdx.x * blockDim.x + threadIdx.x;
    const int R = (S + 15) >> 4;

    // zero-init ray bounds (grid covers R >= n_rays in this problem; strided for safety)
    for (int j = r; j < n_rays; j += gridDim.x * blockDim.x) { g_rs[j] = 0; g_re[j] = 0; }

    if (r >= R) return;
    const int base = r << 4;

    if (base + 16 <= S) {
        const float4* ts4 = reinterpret_cast<const float4*>(ts + base);
        const float4* te4 = reinterpret_cast<const float4*>(te + base);
        const float4* sg4 = reinterpret_cast<const float4*>(sg + base);
        float4*       sd4 = reinterpret_cast<float4*>(g_sdt + base);
        float acc = 0.0f;
        #pragma unroll
        for (int q = 0; q < 4; q++) {
            const float4 a = ts4[q], b = te4[q], s = sg4[q];
            float4 v;
            v.x = __fmul_rn(s.x, __fsub_rn(b.x, a.x));
            v.y = __fmul_rn(s.y, __fsub_rn(b.y, a.y));
            v.z = __fmul_rn(s.z, __fsub_rn(b.z, a.z));
            v.w = __fmul_rn(s.w, __fsub_rn(b.w, a.w));
            sd4[q] = v;
            acc = __fadd_rn(acc, v.x);   // exact fold-left order preserved
            acc = __fadd_rn(acc, v.y);
            acc = __fadd_rn(acc, v.z);
            acc = __fadd_rn(acc, v.w);
        }
        g_l1[r] = acc;
    } else {
        const int lim = S - base;
        float acc = 0.0f;
        for (int k = 0; k < lim; k++) {
            const int i = base + k;
            const float v = __fmul_rn(sg[i], __fsub_rn(te[i], ts[i]));
            g_sdt[i] = v;
            acc = __fadd_rn(acc, v);
        }
        g_l1[r] = acc;
    }
}

// ---------------------------------------------------------------------------
// K2: generic row fold (lvl1 -> lvl2 totals)
// ---------------------------------------------------------------------------
__global__ __launch_bounds__(256)
void k2_fold(const float* __restrict__ in, int n, float* __restrict__ out)
{
    const int r = blockIdx.x * blockDim.x + threadIdx.x;
    const int R = (n + 15) >> 4;
    if (r >= R) return;
    const int base = r << 4;
    const int lim  = min(16, n - base);
    float acc = 0.0f;
    #pragma unroll
    for (int k = 0; k < 16; k++)
        if (k < lim) acc = __fadd_rn(acc, in[base + k]);
    out[r] = acc;
}

// ---------------------------------------------------------------------------
// K3: single-CTA exact radix-16 scan of a[0..n), n <= 16384.
// Replicates the recursive rewrite: fold rows -> recurse -> downsweep.
// ---------------------------------------------------------------------------
__device__ __forceinline__ void seq_scan(float* a, int n) {
    float acc = 0.0f;
    for (int i = 0; i < n; i++) { acc = __fadd_rn(acc, a[i]); a[i] = acc; }
}

__global__ __launch_bounds__(1024)
void k3_midscan(float* __restrict__ a, int n)
{
    __shared__ float b1[1024], b2[64], b3[4];
    const int tid = threadIdx.x;

    if (n <= 16) { if (tid == 0) seq_scan(a, n); return; }

    const int m1 = (n + 15) >> 4;
    // up: a -> b1
    for (int q = tid; q < m1; q += 1024) {
        const int base = q << 4, lim = min(16, n - base);
        float acc = 0.0f;
        for (int k = 0; k < lim; k++) acc = __fadd_rn(acc, a[base + k]);
        b1[q] = acc;
    }
    __syncthreads();

    if (m1 <= 16) {
        if (tid == 0) seq_scan(b1, m1);
        __syncthreads();
    } else {
        const int m2 = (m1 + 15) >> 4;
        if (tid < m2) {
            const int base = tid << 4, lim = min(16, m1 - base);
            float acc = 0.0f;
            for (int k = 0; k < lim; k++) acc = __fadd_rn(acc, b1[base + k]);
            b2[tid] = acc;
        }
        __syncthreads();
        if (m2 <= 16) {
            if (tid == 0) seq_scan(b2, m2);
            __syncthreads();
        } else {
            const int m3 = (m2 + 15) >> 4;        // <= 4 for n <= 16384
            if (tid < m3) {
                const int base = tid << 4, lim = min(16, m2 - base);
                float acc = 0.0f;
                for (int k = 0; k < lim; k++) acc = __fadd_rn(acc, b2[base + k]);
                b3[tid] = acc;
            }
            __syncthreads();
            if (tid == 0) seq_scan(b3, m3);
            __syncthreads();
            if (tid < m3) {                        // down b2 rows
                const int base = tid << 4, lim = min(16, m2 - base);
                float acc = 0.0f;
                const float p = (tid > 0) ? b3[tid - 1] : 0.0f;
                for (int k = 0; k < lim; k++) {
                    acc = __fadd_rn(acc, b2[base + k]);
                    b2[base + k] = (tid == 0) ? acc : __fadd_rn(acc, p);
                }
            }
            __syncthreads();
        }
        if (tid < m2) {                            // down b1 rows
            const int base = tid << 4, lim = min(16, m1 - base);
            float acc = 0.0f;
            const float p = (tid > 0) ? b2[tid - 1] : 0.0f;
            for (int k = 0; k < lim; k++) {
                acc = __fadd_rn(acc, b1[base + k]);
                b1[base + k] = (tid == 0) ? acc : __fadd_rn(acc, p);
            }
        }
        __syncthreads();
    }
    // down a rows with scanned b1
    for (int q = tid; q < m1; q += 1024) {
        const int base = q << 4, lim = min(16, n - base);
        float acc = 0.0f;
        const float p = (q > 0) ? b1[q - 1] : 0.0f;
        for (int k = 0; k < lim; k++) {
            acc = __fadd_rn(acc, a[base + k]);
            a[base + k] = (q == 0) ? acc : __fadd_rn(acc, p);
        }
    }
}

// ---------------------------------------------------------------------------
// K4: generic downsweep of lvl1 rows using scanned lvl2 (in place)
// ---------------------------------------------------------------------------
__global__ __launch_bounds__(256)
void k4_down(float* __restrict__ a, int n, const float* __restrict__ snext)
{
    const int r = blockIdx.x * blockDim.x + threadIdx.x;
    const int R = (n + 15) >> 4;
    if (r >= R) return;
    const int base = r << 4;
    const int lim  = min(16, n - base);
    float acc = 0.0f;
    const float p = (r > 0) ? snext[r - 1] : 0.0f;
    #pragma unroll
    for (int k = 0; k < 16; k++) {
        if (k < lim) {
            acc = __fadd_rn(acc, a[base + k]);
            a[base + k] = (r == 0) ? acc : __fadd_rn(acc, p);
        }
    }
}

// ---------------------------------------------------------------------------
// K5: final downsweep (g_sdt + scanned lvl1 -> g_c), float4 path, plus
// segment-boundary detection scattering ray start/end.
// ---------------------------------------------------------------------------
__global__ __launch_bounds__(256)
void k5_down0_bounds(const int* __restrict__ idx, int S)
{
    const int r = blockIdx.x * blockDim.x + threadIdx.x;
    const int R = (S + 15) >> 4;
    if (r >= R) return;
    const int base = r << 4;
    const float p = (r > 0) ? g_l1[r - 1] : 0.0f;
    const int prev0 = (base > 0) ? idx[base - 1] : -1;

    if (base + 16 <= S) {
        const float4* sd4 = reinterpret_cast<const float4*>(g_sdt + base);
        const int4*   id4 = reinterpret_cast<const int4*>(idx + base);
        float4*       c4  = reinterpret_cast<float4*>(g_c + base);
        float acc = 0.0f;
        int prev = prev0;
        #pragma unroll
        for (int q = 0; q < 4; q++) {
            const float4 v = sd4[q];
            const int4   d = id4[q];
            float4 c;
            acc = __fadd_rn(acc, v.x); c.x = (r == 0) ? acc : __fadd_rn(acc, p);
            acc = __fadd_rn(acc, v.y); c.y = (r == 0) ? acc : __fadd_rn(acc, p);
            acc = __fadd_rn(acc, v.z); c.z = (r == 0) ? acc : __fadd_rn(acc, p);
            acc = __fadd_rn(acc, v.w); c.w = (r == 0) ? acc : __fadd_rn(acc, p);
            c4[q] = c;
            const int i0 = base + 4 * q;
            if (d.x != prev) { g_rs[d.x] = i0;     if (prev >= 0) g_re[prev] = i0;     }
            if (d.y != d.x)  { g_rs[d.y] = i0 + 1; g_re[d.x] = i0 + 1; }
            if (d.z != d.y)  { g_rs[d.z] = i0 + 2; g_re[d.y] = i0 + 2; }
            if (d.w != d.z)  { g_rs[d.w] = i0 + 3; g_re[d.z] = i0 + 3; }
            prev = d.w;
        }
        if (base + 16 == S) g_re[prev] = S;
    } else {
        const int lim = S - base;
        float acc = 0.0f;
        int prev = prev0;
        for (int k = 0; k < lim; k++) {
            const int i = base + k;
            acc = __fadd_rn(acc, g_sdt[i]);
            g_c[i] = (r == 0) ? acc : __fadd_rn(acc, p);
            const int cur = idx[i];
            if (cur != prev) { g_rs[cur] = i; if (prev >= 0) g_re[prev] = i; }
            prev = cur;
        }
        g_re[prev] = S;
    }
}

// ---------------------------------------------------------------------------
// K6: warp-per-ray render + accumulate (bounds precomputed).
// ---------------------------------------------------------------------------
__global__ __launch_bounds__(K6_THREADS)
void k6_render(const float* __restrict__ hdr,
               float*       __restrict__ out,
               int n_rays)
{
    const int r    = blockIdx.x * WARPS_PER_BLOCK + (threadIdx.x >> 5);
    const int lane = threadIdx.x & 31;
    if (r >= n_rays) return;

    int b = 0;
    if (lane == 0) b = g_rs[r];
    else if (lane == 1) b = g_re[r];
    const int start = __shfl_sync(0xffffffffu, b, 0);
    const int end   = __shfl_sync(0xffffffffu, b, 1);

    if (end <= start) {                       // empty ray
        if (lane == 0)
            reinterpret_cast<float4*>(out)[r] = make_float4(0.f, 0.f, 0.f, 0.f);
        return;
    }

    float e_lead = 0.0f;
    if (lane == 0)
        e_lead = __fsub_rn(g_c[start], g_sdt[start]);
    e_lead = __shfl_sync(0xffffffffu, e_lead, 0);

    float opac = 0.0f, cr = 0.0f, cg = 0.0f, cb = 0.0f;

    for (int base = start; base < end; base += 32) {
        const int i = base + lane;
        if (i < end) {
            const float s  = g_sdt[i];
            const float ci = g_c[i];
            const float d  = __fsub_rn(__fsub_rn(ci, s), e_lead);
            const float trans = expf(-d);
            const float alpha = 1.0f - expf(-s);
            const float w = __fmul_rn(trans, alpha);
            const long hoff = 3l * i;
            opac += w;
            cr += w * __ldg(hdr + hoff + 0);
            cg += w * __ldg(hdr + hoff + 1);
            cb += w * __ldg(hdr + hoff + 2);
        }
    }

    #pragma unroll
    for (int o = 16; o > 0; o >>= 1) {
        opac += __shfl_xor_sync(0xffffffffu, opac, o);
        cr   += __shfl_xor_sync(0xffffffffu, cr,   o);
        cg   += __shfl_xor_sync(0xffffffffu, cg,   o);
        cb   += __shfl_xor_sync(0xffffffffu, cb,   o);
    }

    if (lane == 0)
        reinterpret_cast<float4*>(out)[r] = make_float4(opac, cr, cg, cb);
}

// ---------------------------------------------------------------------------
extern "C" void kernel_launch(void* const* d_in, const int* in_sizes, int n_in,
                              void* d_out, int out_size)
{
    const float* t_starts    = (const float*)d_in[0];
    const float* t_ends      = (const float*)d_in[1];
    const float* sigmas      = (const float*)d_in[2];
    const float* hdr         = (const float*)d_in[3];
    const int*   ray_indices = (const int*)  d_in[4];
    float*       out         = (float*)d_out;

    const int S      = in_sizes[0];
    const int n_rays = out_size / 4;

    const int n1 = (S + 15) >> 4;
    const int n2 = (n1 + 15) >> 4;

    float *l1 = nullptr, *l2 = nullptr;
    cudaGetSymbolAddress((void**)&l1, g_l1);
    cudaGetSymbolAddress((void**)&l2, g_l2);

    const int T = 256;
    k1_sdt_fold<<<(n1 + T - 1) / T, T>>>(t_starts, t_ends, sigmas, S, n_rays);

    if (n1 <= 16) {
        k3_midscan<<<1, 1024>>>(l1, n1);
    } else {
        k2_fold<<<(n2 + T - 1) / T, T>>>(l1, n1, l2);
        k3_midscan<<<1, 1024>>>(l2, n2);
        k4_down<<<(n2 + T - 1) / T, T>>>(l1, n1, l2);
    }

    k5_down0_bounds<<<(n1 + T - 1) / T, T>>>(ray_indices, S);

    const int blocks = (n_rays + WARPS_PER_BLOCK - 1) / WARPS_PER_BLOCK;
    k6_render<<<blocks, K6_THREADS>>>(hdr, out, n_rays);
}

// round 7
// speedup vs baseline: 2.2795x; 1.2426x over previous
#include <cuda_runtime.h>
#include <cuda_bf16.h>

// NeRF render + accumulate, bit-matching XLA:CPU's ReduceWindowRewriter
// (base_length=16) radix-16 cumsum tree. PASSES @ rel_err 1.5e-7.
// R6: k4 (generic downsweep) eliminated — k5 reconstructs its prefix from
// raw l1 / raw l2 / scanned l2 with k4's exact bracketing. k5 also emits
// per-ray e_lead so k6 has no serialized gather at warp start.
// Rounding-critical sequences (unchanged from R4/R5):
//   sdt_i = fmul(sigma_i, fsub(te_i, ts_i))
//   fold-left rows with fadd; c = (row0) ? acc : fadd(acc, prefix)
//   excl = fsub(c, sdt); d = fsub(excl_i, e_lead); w = fmul(exp(-d), 1-exp(-sdt))

#define MAX_S    (1 << 22)
#define N1_MAX   (MAX_S / 16)      // 262144
#define N2_MAX   (N1_MAX / 16)     // 16384
#define MAX_RAYS (1 << 18)
#define WARPS_PER_BLOCK 8
#define K6_THREADS (WARPS_PER_BLOCK * 32)

__device__ __align__(16) float g_sdt[MAX_S];
__device__ __align__(16) float g_c[MAX_S];
__device__ __align__(16) float g_l1[N1_MAX];
__device__ __align__(16) float g_l2[N2_MAX];     // raw row totals of l1
__device__ __align__(16) float g_l2s[N2_MAX];    // scanned l2
__device__ int   g_rs[MAX_RAYS];
__device__ int   g_re[MAX_RAYS];
__device__ float g_elead[MAX_RAYS];

// ---------------------------------------------------------------------------
// K1: sdt = fmul(sg, fsub(te, ts)); fold-left per 16-row -> g_l1.
// Also zero-inits ray bounds.
// ---------------------------------------------------------------------------
__global__ __launch_bounds__(256)
void k1_sdt_fold(const float* __restrict__ ts,
                 const float* __restrict__ te,
                 const float* __restrict__ sg,
                 int S, int n_rays)
{
    const int r = blockIdx.x * blockDim.x + threadIdx.x;
    const int R = (S + 15) >> 4;

    for (int j = r; j < n_rays; j += gridDim.x * blockDim.x) { g_rs[j] = 0; g_re[j] = 0; }

    if (r >= R) return;
    const int base = r << 4;

    if (base + 16 <= S) {
        const float4* ts4 = reinterpret_cast<const float4*>(ts + base);
        const float4* te4 = reinterpret_cast<const float4*>(te + base);
        const float4* sg4 = reinterpret_cast<const float4*>(sg + base);
        float4*       sd4 = reinterpret_cast<float4*>(g_sdt + base);
        float acc = 0.0f;
        #pragma unroll
        for (int q = 0; q < 4; q++) {
            const float4 a = ts4[q], b = te4[q], s = sg4[q];
            float4 v;
            v.x = __fmul_rn(s.x, __fsub_rn(b.x, a.x));
            v.y = __fmul_rn(s.y, __fsub_rn(b.y, a.y));
            v.z = __fmul_rn(s.z, __fsub_rn(b.z, a.z));
            v.w = __fmul_rn(s.w, __fsub_rn(b.w, a.w));
            sd4[q] = v;
            acc = __fadd_rn(acc, v.x);   // exact fold-left order preserved
            acc = __fadd_rn(acc, v.y);
            acc = __fadd_rn(acc, v.z);
            acc = __fadd_rn(acc, v.w);
        }
        g_l1[r] = acc;
    } else {
        const int lim = S - base;
        float acc = 0.0f;
        for (int k = 0; k < lim; k++) {
            const int i = base + k;
            const float v = __fmul_rn(sg[i], __fsub_rn(te[i], ts[i]));
            g_sdt[i] = v;
            acc = __fadd_rn(acc, v);
        }
        g_l1[r] = acc;
    }
}

// ---------------------------------------------------------------------------
// K2: fold l1 rows (16) -> l2 raw totals. float4 loads.
// ---------------------------------------------------------------------------
__global__ __launch_bounds__(256)
void k2_fold(const float* __restrict__ in, int n, float* __restrict__ out)
{
    const int r = blockIdx.x * blockDim.x + threadIdx.x;
    const int R = (n + 15) >> 4;
    if (r >= R) return;
    const int base = r << 4;
    float acc = 0.0f;
    if (base + 16 <= n) {
        const float4* in4 = reinterpret_cast<const float4*>(in + base);
        #pragma unroll
        for (int q = 0; q < 4; q++) {
            const float4 v = in4[q];
            acc = __fadd_rn(acc, v.x);
            acc = __fadd_rn(acc, v.y);
            acc = __fadd_rn(acc, v.z);
            acc = __fadd_rn(acc, v.w);
        }
    } else {
        const int lim = n - base;
        for (int k = 0; k < lim; k++) acc = __fadd_rn(acc, in[base + k]);
    }
    out[r] = acc;
}

// ---------------------------------------------------------------------------
// K3: single-CTA exact radix-16 scan: out = cum(in), n <= 16384. in stays raw.
// ---------------------------------------------------------------------------
__device__ __forceinline__ void seq_scan(float* a, int n) {
    float acc = 0.0f;
    for (int i = 0; i < n; i++) { acc = __fadd_rn(acc, a[i]); a[i] = acc; }
}

__global__ __launch_bounds__(1024)
void k3_midscan(const float* __restrict__ in, float* __restrict__ out, int n)
{
    __shared__ float b1[1024], b2[64], b3[4];
    const int tid = threadIdx.x;

    if (n <= 16) {
        if (tid == 0) {
            float acc = 0.0f;
            for (int i = 0; i < n; i++) { acc = __fadd_rn(acc, in[i]); out[i] = acc; }
        }
        return;
    }

    const int m1 = (n + 15) >> 4;
    for (int q = tid; q < m1; q += 1024) {
        const int base = q << 4, lim = min(16, n - base);
        float acc = 0.0f;
        if (lim == 16) {
            const float4* in4 = reinterpret_cast<const float4*>(in + base);
            #pragma unroll
            for (int t = 0; t < 4; t++) {
                const float4 v = in4[t];
                acc = __fadd_rn(acc, v.x); acc = __fadd_rn(acc, v.y);
                acc = __fadd_rn(acc, v.z); acc = __fadd_rn(acc, v.w);
            }
        } else {
            for (int k = 0; k < lim; k++) acc = __fadd_rn(acc, in[base + k]);
        }
        b1[q] = acc;
    }
    __syncthreads();

    if (m1 <= 16) {
        if (tid == 0) seq_scan(b1, m1);
        __syncthreads();
    } else {
        const int m2 = (m1 + 15) >> 4;
        if (tid < m2) {
            const int base = tid << 4, lim = min(16, m1 - base);
            float acc = 0.0f;
            for (int k = 0; k < lim; k++) acc = __fadd_rn(acc, b1[base + k]);
            b2[tid] = acc;
        }
        __syncthreads();
        if (m2 <= 16) {
            if (tid == 0) seq_scan(b2, m2);
            __syncthreads();
        } else {
            const int m3 = (m2 + 15) >> 4;      // <= 4
            if (tid < m3) {
                const int base = tid << 4, lim = min(16, m2 - base);
                float acc = 0.0f;
                for (int k = 0; k < lim; k++) acc = __fadd_rn(acc, b2[base + k]);
                b3[tid] = acc;
            }
            __syncthreads();
            if (tid == 0) seq_scan(b3, m3);
            __syncthreads();
            if (tid < m3) {
                const int base = tid << 4, lim = min(16, m2 - base);
                float acc = 0.0f;
                const float p = (tid > 0) ? b3[tid - 1] : 0.0f;
                for (int k = 0; k < lim; k++) {
                    acc = __fadd_rn(acc, b2[base + k]);
                    b2[base + k] = (tid == 0) ? acc : __fadd_rn(acc, p);
                }
            }
            __syncthreads();
        }
        if (tid < m2) {
            const int base = tid << 4, lim = min(16, m1 - base);
            float acc = 0.0f;
            const float p = (tid > 0) ? b2[tid - 1] : 0.0f;
            for (int k = 0; k < lim; k++) {
                acc = __fadd_rn(acc, b1[base + k]);
                b1[base + k] = (tid == 0) ? acc : __fadd_rn(acc, p);
            }
        }
        __syncthreads();
    }
    for (int q = tid; q < m1; q += 1024) {
        const int base = q << 4, lim = min(16, n - base);
        float acc = 0.0f;
        const float p = (q > 0) ? b1[q - 1] : 0.0f;
        for (int k = 0; k < lim; k++) {
            acc = __fadd_rn(acc, in[base + k]);
            out[base + k] = (q == 0) ? acc : __fadd_rn(acc, p);
        }
    }
}

// ---------------------------------------------------------------------------
// K5: final downsweep. Prefix reconstructed with k4's exact bracketing from
// raw l1, raw l2, scanned l2. Also: segment bounds + per-ray e_lead.
// ---------------------------------------------------------------------------
__global__ __launch_bounds__(256)
void k5_down0_bounds(const int* __restrict__ idx, int S, int n1)
{
    const int r = blockIdx.x * blockDim.x + threadIdx.x;
    const int R = (S + 15) >> 4;
    if (r >= R) return;
    const int base = r << 4;

    // --- reconstruct prefix p = scanned_l1[r-1] (k4 bracketing) ---
    float p = 0.0f;
    if (r != 0) {
        const int q = r >> 4, j = r & 15;
        if (j > 0) {
            const int rowb = q << 4;
            float pl1 = 0.0f;
            for (int k = 0; k < j; k++)                    // fold-left, j terms
                pl1 = __fadd_rn(pl1, __ldg(g_l1 + rowb + k));
            p = (q == 0) ? pl1 : __fadd_rn(pl1, __ldg(g_l2s + q - 1));
        } else {
            p = (q == 1) ? __ldg(g_l2 + 0)
                         : __fadd_rn(__ldg(g_l2 + q - 1), __ldg(g_l2s + q - 2));
        }
    }

    const int prev0 = (base > 0) ? __ldg(idx + base - 1) : -1;

    if (base + 16 <= S) {
        const float4* sd4 = reinterpret_cast<const float4*>(g_sdt + base);
        const int4*   id4 = reinterpret_cast<const int4*>(idx + base);
        float4*       c4  = reinterpret_cast<float4*>(g_c + base);

        float sd[16]; int id[16];
        #pragma unroll
        for (int q = 0; q < 4; q++) {
            const float4 v = sd4[q];
            sd[4*q+0] = v.x; sd[4*q+1] = v.y; sd[4*q+2] = v.z; sd[4*q+3] = v.w;
            const int4 d = id4[q];
            id[4*q+0] = d.x; id[4*q+1] = d.y; id[4*q+2] = d.z; id[4*q+3] = d.w;
        }

        float cv[16];
        float acc = 0.0f;
        #pragma unroll
        for (int k = 0; k < 16; k++) {
            acc = __fadd_rn(acc, sd[k]);
            cv[k] = (r == 0) ? acc : __fadd_rn(acc, p);
        }

        int prev = prev0;
        #pragma unroll
        for (int k = 0; k < 16; k++) {
            const int cur = id[k];
            if (cur != prev) {
                const int i = base + k;
                g_rs[cur] = i;
                if (prev >= 0) g_re[prev] = i;
                g_elead[cur] = __fsub_rn(cv[k], sd[k]);    // excl at lead
            }
            prev = cur;
        }
        if (base + 16 == S) g_re[prev] = S;

        #pragma unroll
        for (int q = 0; q < 4; q++)
            c4[q] = make_float4(cv[4*q+0], cv[4*q+1], cv[4*q+2], cv[4*q+3]);
    } else {
        const int lim = S - base;
        float acc = 0.0f;
        int prev = prev0;
        for (int k = 0; k < lim; k++) {
            const int i = base + k;
            const float s = g_sdt[i];
            acc = __fadd_rn(acc, s);
            const float c = (r == 0) ? acc : __fadd_rn(acc, p);
            g_c[i] = c;
            const int cur = idx[i];
            if (cur != prev) {
                g_rs[cur] = i;
                if (prev >= 0) g_re[prev] = i;
                g_elead[cur] = __fsub_rn(c, s);
            }
            prev = cur;
        }
        g_re[prev] = S;
    }
}

// ---------------------------------------------------------------------------
// K6: warp-per-ray render + accumulate (bounds + e_lead precomputed).
// ---------------------------------------------------------------------------
__global__ __launch_bounds__(K6_THREADS)
void k6_render(const float* __restrict__ hdr,
               float*       __restrict__ out,
               int n_rays)
{
    const int r    = blockIdx.x * WARPS_PER_BLOCK + (threadIdx.x >> 5);
    const int lane = threadIdx.x & 31;
    if (r >= n_rays) return;

    int b = 0;
    float el = 0.0f;
    if (lane == 0)      { b = g_rs[r]; el = g_elead[r]; }
    else if (lane == 1)   b = g_re[r];
    const int start = __shfl_sync(0xffffffffu, b, 0);
    const int end   = __shfl_sync(0xffffffffu, b, 1);

    if (end <= start) {
        if (lane == 0)
            reinterpret_cast<float4*>(out)[r] = make_float4(0.f, 0.f, 0.f, 0.f);
        return;
    }
    const float e_lead = __shfl_sync(0xffffffffu, el, 0);

    float opac = 0.0f, cr = 0.0f, cg = 0.0f, cb = 0.0f;

    for (int base = start; base < end; base += 32) {
        const int i = base + lane;
        if (i < end) {
            const float s  = __ldg(g_sdt + i);
            const float ci = __ldg(g_c + i);
            const float d  = __fsub_rn(__fsub_rn(ci, s), e_lead);
            const float trans = expf(-d);
            const float alpha = 1.0f - expf(-s);
            const float w = __fmul_rn(trans, alpha);
            const long hoff = 3l * i;
            opac += w;
            cr += w * __ldg(hdr + hoff + 0);
            cg += w * __ldg(hdr + hoff + 1);
            cb += w * __ldg(hdr + hoff + 2);
        }
    }

    #pragma unroll
    for (int o = 16; o > 0; o >>= 1) {
        opac += __shfl_xor_sync(0xffffffffu, opac, o);
        cr   += __shfl_xor_sync(0xffffffffu, cr,   o);
        cg   += __shfl_xor_sync(0xffffffffu, cg,   o);
        cb   += __shfl_xor_sync(0xffffffffu, cb,   o);
    }

    if (lane == 0)
        reinterpret_cast<float4*>(out)[r] = make_float4(opac, cr, cg, cb);
}

// ---------------------------------------------------------------------------
extern "C" void kernel_launch(void* const* d_in, const int* in_sizes, int n_in,
                              void* d_out, int out_size)
{
    const float* t_starts    = (const float*)d_in[0];
    const float* t_ends      = (const float*)d_in[1];
    const float* sigmas      = (const float*)d_in[2];
    const float* hdr         = (const float*)d_in[3];
    const int*   ray_indices = (const int*)  d_in[4];
    float*       out         = (float*)d_out;

    const int S      = in_sizes[0];
    const int n_rays = out_size / 4;

    const int n1 = (S + 15) >> 4;
    const int n2 = (n1 + 15) >> 4;

    float *l1 = nullptr, *l2 = nullptr, *l2s = nullptr;
    cudaGetSymbolAddress((void**)&l1,  g_l1);
    cudaGetSymbolAddress((void**)&l2,  g_l2);
    cudaGetSymbolAddress((void**)&l2s, g_l2s);

    const int T = 256;
    k1_sdt_fold<<<(n1 + T - 1) / T, T>>>(t_starts, t_ends, sigmas, S, n_rays);

    if (n1 <= 16) {
        // tiny-S fallback: scan l1 directly into l2s? — keep generic path:
        k3_midscan<<<1, 1024>>>(l1, l2s, n1);
        // emulate: for this degenerate case, treat l2/l2s consistently by
        // copying scanned l1 into l2s and raw into l2 (k5 handles via j>0/q==0).
        // (S <= 256 never occurs for this problem; path kept for safety.)
        k2_fold<<<1, T>>>(l1, n1, l2);
    } else {
        k2_fold<<<(n2 + T - 1) / T, T>>>(l1, n1, l2);
        k3_midscan<<<1, 1024>>>(l2, l2s, n2);
    }

    k5_down0_bounds<<<(n1 + T - 1) / T, T>>>(ray_indices, S, n1);

    const int blocks = (n_rays + WARPS_PER_BLOCK - 1) / WARPS_PER_BLOCK;
    k6_render<<<blocks, K6_THREADS>>>(hdr, out, n_rays);
}